// round 11
// baseline (speedup 1.0000x reference)
#include <cuda_runtime.h>
#include <cuda_fp16.h>
#include <cstdint>

#define CC 256
#define WW 128
#define HH 64
#define BB 2
#define NCOL (BB*HH)
#define HO 256
#define WO 512
#define NOUT (BB*HO*WO)
#define NROWS 512             // output rows (b,i)

// per-fill transaction bytes: remote B half only = 256 threads * 2 * 4B = 2048
#define TXB 2048u

__device__ __half g_M[CC*CC];            // center-tap weights fp16, row-major [o][c]
__device__ float  g_upart[2][NCOL*WW];   // per-rank partial u
__device__ float  g_psum[NROWS];
__device__ float  g_psumsq[NROWS];

__device__ __forceinline__ uint32_t smem_u32(const void* p) {
    uint32_t a;
    asm("{ .reg .u64 t; cvta.to.shared.u64 t, %1; cvt.u32.u64 %0, t; }"
        : "=r"(a) : "l"(p));
    return a;
}
__device__ __forceinline__ uint32_t cluster_rank() {
    uint32_t r;
    asm("mov.u32 %0, %%cluster_ctarank;" : "=r"(r));
    return r;
}
__device__ __forceinline__ uint32_t mapa_u32(uint32_t addr, uint32_t rank) {
    uint32_t r;
    asm("mapa.shared::cluster.u32 %0, %1, %2;" : "=r"(r) : "r"(addr), "r"(rank));
    return r;
}
#define ST_ASYNC_U32(addr, val, mbar)                                         \
    asm volatile("st.async.shared::cluster.mbarrier::complete_tx::bytes.u32 " \
                 "[%0], %1, [%2];" :: "r"(addr), "r"(val), "r"(mbar) : "memory")
#define MBAR_INIT(mbar, cnt)                                                  \
    asm volatile("mbarrier.init.shared.b64 [%0], %1;"                         \
                 :: "r"(mbar), "r"((uint32_t)(cnt)) : "memory")
#define MBAR_EXPECT_TX(mbar, bytes)                                           \
    asm volatile("mbarrier.arrive.expect_tx.shared::cta.b64 _, [%0], %1;"     \
                 :: "r"(mbar), "r"((uint32_t)(bytes)) : "memory")
#define MBAR_WAIT(mbar, parity) do {                                          \
    uint32_t _m = (mbar), _p = (parity), _done;                               \
    asm volatile("{ .reg .pred p;\n\t"                                        \
        "mbarrier.try_wait.parity.acquire.cluster.shared::cta.b64 p, [%1], %2;\n\t" \
        "selp.b32 %0, 1, 0, p; }"                                             \
        : "=r"(_done) : "r"(_m), "r"(_p) : "memory");                         \
    if (!_done) {                                                             \
        asm volatile("{ .reg .pred P1;\n\t"                                   \
            "WL_%=:\n\t"                                                      \
            "mbarrier.try_wait.parity.acquire.cluster.shared::cta.b64 P1, [%0], %1, 0x989680;\n\t" \
            "@P1 bra.uni WD_%=;\n\t"                                          \
            "bra.uni WL_%=;\n\t"                                              \
            "WD_%=: }" :: "r"(_m), "r"(_p) : "memory");                       \
    }                                                                         \
} while (0)
#define CLUSTER_SYNC() do {                                                   \
    asm volatile("barrier.cluster.arrive.aligned;" ::: "memory");             \
    asm volatile("barrier.cluster.wait.aligned;"   ::: "memory");             \
} while (0)

// ===========================================================================
__global__ void extract_M_kernel(const float* __restrict__ convw) {
    int i = blockIdx.x * 256 + threadIdx.x;
    g_M[i] = __float2half(convw[i * 9 + 4]);
}

// ===========================================================================
// 2-CTA-cluster HMMA double scan, k-split ordering. 64 CTAs = 32 clusters x
// 4 columns. Each CTA computes 128 output channels (16 MMAs/warp/step) in two
// phases: LOCAL k-half first (own channels, delivered by plain STS +
// __syncthreads), then REMOTE k-half (peer channels via st.async, whose DSMEM
// flight is hidden behind the local phase's LDSM+MMA issue).
#define MMA_ASM(dd, a, b0r, b1r)                                              \
    asm volatile(                                                             \
        "mma.sync.aligned.m16n8k16.row.col.f32.f16.f16.f32 "                  \
        "{%0,%1,%2,%3}, {%4,%5,%6,%7}, {%8,%9}, {%0,%1,%2,%3};"               \
        : "+f"((dd)[0]), "+f"((dd)[1]), "+f"((dd)[2]), "+f"((dd)[3])          \
        : "r"((a)[0]), "r"((a)[1]), "r"((a)[2]), "r"((a)[3]),                 \
          "r"(b0r), "r"(b1r))

#define LDSM_T(L, addr)                                                       \
    asm volatile(                                                             \
        "ldmatrix.sync.aligned.m8n8.x4.trans.shared.b16 {%0,%1,%2,%3}, [%4];" \
        : "=r"((L)[0]), "=r"((L)[1]), "=r"((L)[2]), "=r"((L)[3])              \
        : "r"(addr))

__global__ void __launch_bounds__(256, 1) __cluster_dims__(2, 1, 1)
scnn_hmma_kernel(const float* __restrict__ p2, const float* __restrict__ w1g) {
    __shared__ __align__(128) __half Bbuf[2][CC * 8];   // [buf][k*8 + n] 2x4KB
    __shared__ float wsum[2][8][4];
    __shared__ __align__(8) unsigned long long mbar[2];

    const int tid  = threadIdx.x;
    const int wid  = tid >> 5;
    const int lane = tid & 31;
    const int tg   = lane & 3;
    const int g    = lane >> 2;
    const int col0 = (blockIdx.x >> 1) * 4;
    const int col  = col0 + tg;
    const int b    = col >> 6;
    const int h    = col & 63;
    const uint32_t rank = cluster_rank();
    const uint32_t peer = rank ^ 1u;
    const int localm8 = (int)rank * 4;      // our k-chunks [rank*4, rank*4+4)
    const int peerm8  = (int)peer * 4;

    // ---- A fragments: this CTA's M rows [rank*128 + 16*wid, +16)
    uint32_t A[16][4];
    const int rlo = (int)rank * 128 + 16 * wid + g;
    {
        const uint32_t* Mlo = reinterpret_cast<const uint32_t*>(g_M + rlo * CC);
        const uint32_t* Mhi = reinterpret_cast<const uint32_t*>(g_M + (rlo + 8) * CC);
#pragma unroll
        for (int kt = 0; kt < 16; kt++) {
            A[kt][0] = Mlo[kt * 8 + tg];
            A[kt][1] = Mhi[kt * 8 + tg];
            A[kt][2] = Mlo[kt * 8 + tg + 4];
            A[kt][3] = Mhi[kt * 8 + tg + 4];
        }
    }

    const int ch0 = rlo;
    const int ch1 = rlo + 8;
    const float w1a = w1g[ch0];
    const float w1b = w1g[ch1];

    const float4* xpa = reinterpret_cast<const float4*>(
        p2 + ((size_t)(b * CC + ch0) * HH + h) * WW);
    const float4* xpb = reinterpret_cast<const float4*>(
        p2 + ((size_t)(b * CC + ch1) * HH + h) * WW);

    const uint32_t b32    = smem_u32(&Bbuf[0][0]);
    const uint32_t bar32  = smem_u32(&mbar[0]);
    const uint32_t b32r   = mapa_u32(b32,  peer);
    const uint32_t bar32r = mapa_u32(bar32, peer);
    const uint32_t lmaddr = b32 + (uint32_t)lane * 16u;
    const uint32_t bo0 = (uint32_t)(ch0 * 16 + tg * 4);
    const uint32_t bo1 = (uint32_t)(ch1 * 16 + tg * 4);

    if (tid == 0) { MBAR_INIT(bar32, 1); MBAR_INIT(bar32 + 8, 1); }
    __syncthreads();
    CLUSTER_SYNC();
    if (tid == 0) {
        MBAR_EXPECT_TX(bar32,     TXB);   // fill 0 of buffer 0 (step 0)
        MBAR_EXPECT_TX(bar32 + 8, TXB);   // fill 0 of buffer 1 (step 1)
    }

    // ---- step 0: s1[0] = s2[0] = x[:,0] -> buffer 0 (local STS + remote async)
    float4 cura = xpa[0], curb = xpb[0];
    float4 nxta, nxtb;
    {
        float usum = w1a * cura.x + w1b * curb.x;
        usum += __shfl_xor_sync(0xffffffffu, usum, 4);
        usum += __shfl_xor_sync(0xffffffffu, usum, 8);
        usum += __shfl_xor_sync(0xffffffffu, usum, 16);
        if (lane < 4) wsum[0][wid][lane] = usum;

        __half2 v0h = __halves2half2(__float2half_rn(cura.x), __float2half_rn(cura.x));
        __half2 v1h = __halves2half2(__float2half_rn(curb.x), __float2half_rn(curb.x));
        uint32_t v0 = *reinterpret_cast<uint32_t*>(&v0h);
        uint32_t v1 = *reinterpret_cast<uint32_t*>(&v1h);
        *(__half2*)&Bbuf[0][ch0 * 8 + 2 * tg] = v0h;
        *(__half2*)&Bbuf[0][ch1 * 8 + 2 * tg] = v1h;
        ST_ASYNC_U32(b32r + bo0, v0, bar32r);
        ST_ASYNC_U32(b32r + bo1, v1, bar32r);
    }

    for (int w = 1; w < WW; w++) {
        const int rb = (w - 1) & 1;
        const int wb = rb ^ 1;
        __syncthreads();                   // local B half + wsum of step w-1

        const uint32_t base = lmaddr + (uint32_t)rb * (CC * 8 * 2);

        // ---- LOCAL phase: our own k-chunks (no cluster latency)
        uint32_t Lc[4][4];
#pragma unroll
        for (int i = 0; i < 4; i++)
            LDSM_T(Lc[i], base + (uint32_t)((localm8 + i) * 512));

        // drain step w-1's u partial (4 threads; overlaps local MMA stream)
        if (tid < 4) {
            float s = 0.f;
#pragma unroll
            for (int q8 = 0; q8 < 8; q8++) s += wsum[rb][q8][tid];
            g_upart[rank][(col0 + tid) * WW + (WW - w)] = s;
        }

        float d[4] = {0.f, 0.f, 0.f, 0.f};
        float e[4] = {0.f, 0.f, 0.f, 0.f};
#pragma unroll
        for (int i = 0; i < 4; i++) {
            const int m8 = localm8 + i;
            MMA_ASM(d, A[2 * m8],     Lc[i][0], Lc[i][1]);
            MMA_ASM(e, A[2 * m8 + 1], Lc[i][2], Lc[i][3]);
        }

        const int j = (w - 1) & 3;
        if (j == 0 && w + 4 <= WW) {       // prefetch next float4 group
            nxta = xpa[(w + 3) >> 2];
            nxtb = xpb[(w + 3) >> 2];
        }

        // ---- REMOTE phase: peer's k-chunks (flight hidden by local phase)
        const uint32_t barL = bar32 + (uint32_t)rb * 8u;
        MBAR_WAIT(barL, (uint32_t)(((w - 1) >> 1) & 1));
        if (tid == 0 && w <= 125) MBAR_EXPECT_TX(barL, TXB);

        uint32_t Lr[4][4];
#pragma unroll
        for (int i = 0; i < 4; i++)
            LDSM_T(Lr[i], base + (uint32_t)((peerm8 + i) * 512));
#pragma unroll
        for (int i = 0; i < 4; i++) {
            const int m8 = peerm8 + i;
            MMA_ASM(d, A[2 * m8],     Lr[i][0], Lr[i][1]);
            MMA_ASM(e, A[2 * m8 + 1], Lr[i][2], Lr[i][3]);
        }

        float xa = (j == 0) ? cura.y : (j == 1) ? cura.z : (j == 2) ? cura.w : nxta.x;
        float xb = (j == 0) ? curb.y : (j == 1) ? curb.z : (j == 2) ? curb.w : nxtb.x;

        float s1a = xa + fmaxf(d[0] + e[0], 0.f);
        float s2a = s1a + fmaxf(d[1] + e[1], 0.f);
        float s1b = xb + fmaxf(d[2] + e[2], 0.f);
        float s2b = s1b + fmaxf(d[3] + e[3], 0.f);

        float usum = w1a * s2a + w1b * s2b;
        usum += __shfl_xor_sync(0xffffffffu, usum, 4);
        usum += __shfl_xor_sync(0xffffffffu, usum, 8);
        usum += __shfl_xor_sync(0xffffffffu, usum, 16);
        if (lane < 4) wsum[wb][wid][lane] = usum;

        if (w < WW - 1) {
            const uint32_t barWbR = bar32r + (uint32_t)wb * 8u;
            const uint32_t bufOff = (uint32_t)wb * (CC * 8 * 2);
            __half2 v0h = __floats2half2_rn(s1a, s2a);
            __half2 v1h = __floats2half2_rn(s1b, s2b);
            uint32_t v0 = *reinterpret_cast<uint32_t*>(&v0h);
            uint32_t v1 = *reinterpret_cast<uint32_t*>(&v1h);
            *(__half2*)&Bbuf[wb][ch0 * 8 + 2 * tg] = v0h;   // local half: plain
            *(__half2*)&Bbuf[wb][ch1 * 8 + 2 * tg] = v1h;
            ST_ASYNC_U32(b32r + bufOff + bo0, v0, barWbR);  // remote half: async
            ST_ASYNC_U32(b32r + bufOff + bo1, v1, barWbR);
        }

        if (j == 3) { cura = nxta; curb = nxtb; }
    }

    __syncthreads();
    if (tid < 4) {
        float s = 0.f;
#pragma unroll
        for (int q8 = 0; q8 < 8; q8++) s += wsum[1][q8][tid];   // w=127 -> buf 1
        g_upart[rank][(col0 + tid) * WW + 0] = s;
    }
    CLUSTER_SYNC();
}

// ===========================================================================
__device__ __forceinline__ void stage_rows(float* su0, float* su1,
                                           int b, int i, float& wy) {
    float ys = (float)i * (63.0f / 255.0f);
    int y0 = (int)ys;
    wy = ys - (float)y0;
    int y1 = min(y0 + 1, HH - 1);
    int t = threadIdx.x;
    if (t < 128)
        su0[t] = g_upart[0][(b * HH + y0) * WW + t]
               + g_upart[1][(b * HH + y0) * WW + t];
    else if (t < 256)
        su1[t - 128] = g_upart[0][(b * HH + y1) * WW + (t - 128)]
                     + g_upart[1][(b * HH + y1) * WW + (t - 128)];
}

__device__ __forceinline__ float bilin(const float* su0, const float* su1,
                                       int j, float wy) {
    float xs = (float)j * (127.0f / 511.0f);
    int x0 = (int)xs;
    float wx = xs - (float)x0;
    int x1 = min(x0 + 1, WW - 1);
    float r0 = su0[x0] * (1.f - wy) + su1[x0] * wy;
    float r1 = su0[x1] * (1.f - wy) + su1[x1] * wy;
    return r0 * (1.f - wx) + r1 * wx;
}

__global__ void stats_kernel() {
    __shared__ float su0[128], su1[128];
    __shared__ float rs[8], rq[8];
    int row = blockIdx.x;
    int b = row >> 8, i = row & 255;
    float wy;
    stage_rows(su0, su1, b, i, wy);
    __syncthreads();

    int t = threadIdx.x;
    float sum = 0.f, sq = 0.f;
#pragma unroll
    for (int rr = 0; rr < 2; rr++) {
        float v = bilin(su0, su1, t + rr * 256, wy);
        sum += v;
        sq  += v * v;
    }
#pragma unroll
    for (int o = 16; o; o >>= 1) {
        sum += __shfl_xor_sync(0xffffffffu, sum, o);
        sq  += __shfl_xor_sync(0xffffffffu, sq,  o);
    }
    if ((t & 31) == 0) { rs[t >> 5] = sum; rq[t >> 5] = sq; }
    __syncthreads();
    if (t == 0) {
        float a = 0.f, c = 0.f;
#pragma unroll
        for (int k = 0; k < 8; k++) { a += rs[k]; c += rq[k]; }
        g_psum[row] = a; g_psumsq[row] = c;
    }
}

__global__ void output_kernel(float* __restrict__ out,
                              const float* __restrict__ gamma,
                              const float* __restrict__ beta) {
    __shared__ float su0[128], su1[128];
    __shared__ float rs[8], rq[8];
    __shared__ float stats2[2];
    int row = blockIdx.x;
    int b = row >> 8, i = row & 255;
    float wy;
    stage_rows(su0, su1, b, i, wy);

    int t = threadIdx.x;
    float sum = g_psum[t] + g_psum[t + 256];
    float sq  = g_psumsq[t] + g_psumsq[t + 256];
#pragma unroll
    for (int o = 16; o; o >>= 1) {
        sum += __shfl_xor_sync(0xffffffffu, sum, o);
        sq  += __shfl_xor_sync(0xffffffffu, sq,  o);
    }
    if ((t & 31) == 0) { rs[t >> 5] = sum; rq[t >> 5] = sq; }
    __syncthreads();
    if (t == 0) {
        float a = 0.f, c = 0.f;
#pragma unroll
        for (int k = 0; k < 8; k++) { a += rs[k]; c += rq[k]; }
        float inv_n = 1.0f / (float)NOUT;
        float mean  = a * inv_n;
        float var   = c * inv_n - mean * mean;
        stats2[0] = mean;
        stats2[1] = rsqrtf(var + 1e-5f);
    }
    __syncthreads();

    float mean = stats2[0], istd = stats2[1];
    float gm = gamma[0], bt = beta[0];
#pragma unroll
    for (int rr = 0; rr < 2; rr++) {
        int j = t + rr * 256;
        float v = bilin(su0, su1, j, wy);
        float y = (v - mean) * istd * gm + bt;
        out[row * WO + j] = 1.0f / (1.0f + expf(-y));
    }
}

// ===========================================================================
extern "C" void kernel_launch(void* const* d_in, const int* in_sizes, int n_in,
                              void* d_out, int out_size) {
    const float* p2    = (const float*)d_in[0];
    const float* convw = (const float*)d_in[1];
    const float* conv1 = (const float*)d_in[2];
    const float* gamma = (const float*)d_in[3];
    const float* beta  = (const float*)d_in[4];
    float* out = (float*)d_out;

    extract_M_kernel<<<256, 256>>>(convw);
    scnn_hmma_kernel<<<64, 256>>>(p2, conv1);
    stats_kernel<<<NROWS, 256>>>();
    output_kernel<<<NROWS, 256>>>(out, gamma, beta);
}